// round 7
// baseline (speedup 1.0000x reference)
#include <cuda_runtime.h>
#include <cuda_bf16.h>
#include <cstdint>

// Problem constants
#define NVEC   65536      // N = B*H*W = 16*64*64
#define KCODE  1024
#define DIM    64
#define HW     4096       // H*W
#define CHW    262144     // C*H*W

// Output layout (concatenated in reference return order, all fp32)
#define QUANT_OFF 0
#define LOSS_OFF  4194304
#define PERP_OFF  4194305
#define NCS_OFF   4194306
#define EMAW_OFF  4195330
#define EMBW_OFF  4260866

#define NTILES   1024     // 64-row work tiles
#define GRID_ARG 296      // 148 SMs * 2 blocks (smem-limited)

// dynamic smem word map (uint32 units)
#define XS_W   0          // xs[3][64 rows][36]  (32 used + 4 pad) = 6912 words
#define WS_W   6912       // ws[3][128 codes][36]               = 13824 words
#define W2_W   20736      // w2s[1024]
#define SC_W   21760      // s_code[64]
#define TL_W   21824      // s_tile
#define SMEM_ARG 87424    // bytes

// Scratch (device globals — no allocation allowed)
__device__ int   g_idx[NVEC];
__device__ uint32_t g_Wp[3 * KCODE * 32];   // [split][code][k-pair] packed bf16x2
__device__ float g_w2[KCODE];
__device__ int   g_counts[KCODE];
__device__ __align__(16) float g_dw[KCODE * DIM];
__device__ __align__(16) float g_embed[KCODE * DIM];
__device__ float g_loss;
__device__ int   g_tile;

// exact 3-way bf16 split: x = f(s0)+f(s1)+f(s2) EXACTLY (8+8+8 >= 24 bits)
__device__ __forceinline__ uint32_t bf16rn(float f) {
    uint32_t u = __float_as_uint(f);
    return (u + 0x7fffu + ((u >> 16) & 1u)) >> 16;   // RN-even to bf16
}
__device__ __forceinline__ void split3(float v, uint32_t& s0, uint32_t& s1, uint32_t& s2) {
    s0 = bf16rn(v);
    float r  = v - __uint_as_float(s0 << 16);   // exact
    s1 = bf16rn(r);
    float r2 = r - __uint_as_float(s1 << 16);   // exact
    s2 = bf16rn(r2);                            // exact (<=8 bits left)
}

#define MMA_BF16(c0,c1,c2,c3, A, B0, B1)                                        \
    asm volatile("mma.sync.aligned.m16n8k16.row.col.f32.bf16.bf16.f32 "          \
                 "{%0,%1,%2,%3},{%4,%5,%6,%7},{%8,%9},{%0,%1,%2,%3};"           \
                 : "+f"(c0), "+f"(c1), "+f"(c2), "+f"(c3)                       \
                 : "r"((A)[0]), "r"((A)[1]), "r"((A)[2]), "r"((A)[3]),          \
                   "r"(B0), "r"(B1));

// ---------------------------------------------------------------------------
// Kernel A: prep — split codebook to bf16x3 packed pairs, ||w||^2, zero accs
// ---------------------------------------------------------------------------
__global__ void prep_kernel(const float* __restrict__ W) {
    int i = blockIdx.x * 256 + threadIdx.x;   // 0..65535
    g_dw[i] = 0.f;
    if (i < 32768) {                          // i = code*32 + kpair
        int code = i >> 5, kk = i & 31;
        float v0 = W[code * 64 + 2 * kk];
        float v1 = W[code * 64 + 2 * kk + 1];
        uint32_t a0, a1, a2, b0, b1, b2;
        split3(v0, a0, a1, a2);
        split3(v1, b0, b1, b2);
        g_Wp[i]         = a0 | (b0 << 16);    // low half = even k
        g_Wp[32768 + i] = a1 | (b1 << 16);
        g_Wp[65536 + i] = a2 | (b2 << 16);
    }
    if (i < KCODE) {
        g_counts[i] = 0;
        const float* row = W + i * DIM;
        float s = 0.f;
        #pragma unroll
        for (int dd = 0; dd < DIM; ++dd) s = fmaf(row[dd], row[dd], s);
        g_w2[i] = s;
    }
    if (i == 0) { g_loss = 0.f; g_tile = 0; }
}

// ---------------------------------------------------------------------------
// Kernel B: persistent tensor-core distance + argmin + counts + dw scatter.
// 128 threads / 4 warps; work tile = 64 rows; warp w owns rows 16w..16w+15.
// dist dot via 8 bf16 mma products (exact 3-way split, lo*lo dropped ~2^-32).
// Padded stride 36 words makes every fragment LDS conflict-free.
// ---------------------------------------------------------------------------
__global__ void __launch_bounds__(128) argmin_kernel(const float* __restrict__ in) {
    extern __shared__ uint32_t sm[];
    uint32_t* xs   = sm + XS_W;               // [s*2304 + row*36 + kpair]
    uint32_t* ws   = sm + WS_W;               // [s*4608 + code*36 + kpair]
    float*    w2s  = (float*)(sm + W2_W);
    int*      s_cd = (int*)(sm + SC_W);
    int*      s_tl = (int*)(sm + TL_W);

    const int tid  = threadIdx.x;
    const int lane = tid & 31;
    const int w    = tid >> 5;        // warp 0..3
    const int g    = lane >> 2;       // group 0..7
    const int t    = lane & 3;        // thread-in-group
    const int r0   = w * 16 + g;      // local rows this thread covers
    const int r1   = r0 + 8;

    for (int i = tid; i < KCODE; i += 128) w2s[i] = g_w2[i];

    for (;;) {
        __syncthreads();              // protect xs/ws/s_cd/s_tl from last iter
        if (tid == 0) *s_tl = atomicAdd(&g_tile, 1);
        __syncthreads();
        const int tile = *s_tl;
        if (tile >= NTILES) return;

        const int rowbase = tile * 64;
        const int b   = rowbase >> 12;
        const int hw0 = rowbase & 4095;
        const float* src = in + (size_t)b * CHW + hw0;

        // --- load + exact-split x tile: xs[s][row][dpair]
        #pragma unroll
        for (int it = 0; it < 4; ++it) {
            int fidx = it * 128 + tid;        // 0..511 over 32 dpairs x 16 c4
            int dp = fidx >> 4;
            int c4 = fidx & 15;
            float4 v0 = __ldg((const float4*)(src + (2 * dp)     * HW + c4 * 4));
            float4 v1 = __ldg((const float4*)(src + (2 * dp + 1) * HW + c4 * 4));
            float e0[4] = {v0.x, v0.y, v0.z, v0.w};
            float e1[4] = {v1.x, v1.y, v1.z, v1.w};
            #pragma unroll
            for (int j = 0; j < 4; ++j) {
                int row = c4 * 4 + j;
                uint32_t a0, a1, a2, b0, b1, b2;
                split3(e0[j], a0, a1, a2);
                split3(e1[j], b0, b1, b2);
                xs[       row * 36 + dp] = a0 | (b0 << 16);
                xs[2304 + row * 36 + dp] = a1 | (b1 << 16);
                xs[4608 + row * 36 + dp] = a2 | (b2 << 16);
            }
        }
        __syncthreads();

        // --- A fragments (resident): [split][kstep][4]
        uint32_t A[3][4][4];
        #pragma unroll
        for (int s = 0; s < 3; ++s)
            #pragma unroll
            for (int ks = 0; ks < 4; ++ks) {
                int base = s * 2304 + 8 * ks + t;
                A[s][ks][0] = xs[base + r0 * 36];
                A[s][ks][1] = xs[base + r1 * 36];
                A[s][ks][2] = xs[base + r0 * 36 + 4];
                A[s][ks][3] = xs[base + r1 * 36 + 4];
            }

        float minv0 = 3.4e38f, minv1 = 3.4e38f;
        int   mink0 = 0,       mink1 = 0;

        for (int ct = 0; ct < 8; ++ct) {
            __syncthreads();          // prior tile reads done
            const int ctbase = ct * 128;
            // cooperative ws tile load (3 splits x 128 codes x 8 uint4)
            #pragma unroll
            for (int i2 = 0; i2 < 24; ++i2) {
                int fidx = i2 * 128 + tid;            // 0..3071
                int s    = fidx >> 10;
                int rem  = fidx & 1023;
                int code = rem >> 3;
                int q    = rem & 7;
                uint4 val = *(const uint4*)(g_Wp + s * 32768 + (ctbase + code) * 32 + q * 4);
                *(uint4*)(ws + s * 4608 + code * 36 + q * 4) = val;
            }
            __syncthreads();

            for (int chunk = 0; chunk < 16; ++chunk) {
                const int n0 = chunk * 8;
                const uint32_t* bp = ws + (n0 + g) * 36;
                float c0 = 0.f, c1 = 0.f, c2 = 0.f, c3 = 0.f;
                #pragma unroll
                for (int ks = 0; ks < 4; ++ks) {
                    uint32_t B0[3], B1[3];
                    #pragma unroll
                    for (int s = 0; s < 3; ++s) {
                        B0[s] = bp[s * 4608 + 8 * ks + t];
                        B1[s] = bp[s * 4608 + 8 * ks + t + 4];
                    }
                    // 8 products, smallest magnitude first (skip lo*lo)
                    MMA_BF16(c0,c1,c2,c3, A[1][ks], B0[2], B1[2]);
                    MMA_BF16(c0,c1,c2,c3, A[2][ks], B0[1], B1[1]);
                    MMA_BF16(c0,c1,c2,c3, A[1][ks], B0[1], B1[1]);
                    MMA_BF16(c0,c1,c2,c3, A[0][ks], B0[2], B1[2]);
                    MMA_BF16(c0,c1,c2,c3, A[2][ks], B0[0], B1[0]);
                    MMA_BF16(c0,c1,c2,c3, A[0][ks], B0[1], B1[1]);
                    MMA_BF16(c0,c1,c2,c3, A[1][ks], B0[0], B1[0]);
                    MMA_BF16(c0,c1,c2,c3, A[0][ks], B0[0], B1[0]);
                }
                // c0:(r0, kg) c1:(r0, kg+1) c2:(r1, kg) c3:(r1, kg+1)
                const int kg = ctbase + n0 + 2 * t;
                float w2a = w2s[kg], w2b = w2s[kg + 1];
                float v00 = fmaf(-2.f, c0, w2a);
                float v01 = fmaf(-2.f, c1, w2b);
                float v10 = fmaf(-2.f, c2, w2a);
                float v11 = fmaf(-2.f, c3, w2b);
                if (v00 < minv0) { minv0 = v00; mink0 = kg; }
                if (v01 < minv0) { minv0 = v01; mink0 = kg + 1; }
                if (v10 < minv1) { minv1 = v10; mink1 = kg; }
                if (v11 < minv1) { minv1 = v11; mink1 = kg + 1; }
            }
        }

        // --- reduce over the 4 lanes sharing a row (cols mod 8 partition)
        #pragma unroll
        for (int off = 2; off > 0; off >>= 1) {
            float v; int ii;
            v  = __shfl_down_sync(0xffffffffu, minv0, off, 4);
            ii = __shfl_down_sync(0xffffffffu, mink0, off, 4);
            if (v < minv0 || (v == minv0 && ii < mink0)) { minv0 = v; mink0 = ii; }
            v  = __shfl_down_sync(0xffffffffu, minv1, off, 4);
            ii = __shfl_down_sync(0xffffffffu, mink1, off, 4);
            if (v < minv1 || (v == minv1 && ii < mink1)) { minv1 = v; mink1 = ii; }
        }
        if ((lane & 3) == 0) {
            g_idx[rowbase + r0] = mink0;
            atomicAdd(&g_counts[mink0], 1);
            s_cd[r0] = mink0;
            g_idx[rowbase + r1] = mink1;
            atomicAdd(&g_counts[mink1], 1);
            s_cd[r1] = mink1;
        }
        __syncthreads();

        // --- dw scatter: exact x reconstructed from the 3 splits
        {
            int row   = tid & 63;
            int dbase = (tid >> 6) * 32;
            int kk2   = s_cd[row];
            float* dst = g_dw + kk2 * DIM + dbase;
            const uint32_t* xr = xs + row * 36 + (dbase >> 1);
            #pragma unroll
            for (int p = 0; p < 16; ++p) {
                uint32_t u0 = xr[p], u1 = xr[2304 + p], u2 = xr[4608 + p];
                float xe = __uint_as_float((u0 & 0xffffu) << 16)
                         + __uint_as_float((u1 & 0xffffu) << 16)
                         + __uint_as_float((u2 & 0xffffu) << 16);
                float xo = __uint_as_float(u0 & 0xffff0000u)
                         + __uint_as_float(u1 & 0xffff0000u)
                         + __uint_as_float(u2 & 0xffff0000u);
                atomicAdd(&dst[2 * p],     xe);
                atomicAdd(&dst[2 * p + 1], xo);
            }
        }
    }
}

// ---------------------------------------------------------------------------
// Kernel C: codebook EMA update + perplexity (single block, 1024 threads)
// ---------------------------------------------------------------------------
__global__ void update_kernel(const float* __restrict__ ecs,
                              const float* __restrict__ emw,
                              float* __restrict__ out) {
    int k = threadIdx.x;
    __shared__ float smr[KCODE];

    float c   = (float)g_counts[k];
    float ncs = ecs[k] * 0.99f + 0.01f * c;
    out[NCS_OFF + k] = ncs;

    smr[k] = ncs; __syncthreads();
    for (int s = 512; s > 0; s >>= 1) {
        if (k < s) smr[k] += smr[k + s];
        __syncthreads();
    }
    float nsum = smr[0];
    __syncthreads();

    float p = c * (1.f / (float)NVEC);
    smr[k] = p * logf(p + 1e-10f);
    __syncthreads();
    for (int s = 512; s > 0; s >>= 1) {
        if (k < s) smr[k] += smr[k + s];
        __syncthreads();
    }
    if (k == 0) out[PERP_OFF] = expf(-smr[0]);

    float normalized = (ncs + 1e-5f) / (nsum + 1024.f * 1e-5f) * nsum;
    float inv = 1.f / normalized;
    #pragma unroll
    for (int d = 0; d < DIM; ++d) {
        int i = k * DIM + d;
        float nw = emw[i] * 0.99f + 0.01f * g_dw[i];
        float e  = nw * inv;
        out[EMAW_OFF + i] = nw;
        out[EMBW_OFF + i] = e;
        g_embed[i] = e;
    }
}

// ---------------------------------------------------------------------------
// Kernel D: quantize + loss (float4 codebook gathers from aligned g_embed)
// ---------------------------------------------------------------------------
__global__ void quant_kernel(const float* __restrict__ in,
                             float* __restrict__ out) {
    int blk = blockIdx.x;
    int b  = blk >> 6;
    int d0 = ((blk >> 2) & 15) * 4;
    int hc = blk & 3;
    int t  = threadIdx.x;

    const size_t pbase = (size_t)b * CHW + (size_t)d0 * HW;
    const int nbase = b * HW;

    float local = 0.f;
    #pragma unroll
    for (int it = 0; it < 4; ++it) {
        int hw = hc * 1024 + it * 256 + t;
        int kk = g_idx[nbase + hw];
        float4 q = *reinterpret_cast<const float4*>(&g_embed[kk * DIM + d0]);
        float qa[4] = {q.x, q.y, q.z, q.w};
        #pragma unroll
        for (int j = 0; j < 4; ++j) {
            size_t off = pbase + (size_t)j * HW + hw;
            float x = in[off];
            out[QUANT_OFF + off] = qa[j];
            float diff = x - qa[j];
            local = fmaf(diff, diff, local);
        }
    }

    #pragma unroll
    for (int o = 16; o > 0; o >>= 1)
        local += __shfl_down_sync(0xffffffff, local, o);
    __shared__ float wsum[8];
    if ((t & 31) == 0) wsum[t >> 5] = local;
    __syncthreads();
    if (t == 0) {
        float s = 0.f;
        #pragma unroll
        for (int i = 0; i < 8; ++i) s += wsum[i];
        atomicAdd(&g_loss, s);
    }
}

__global__ void loss_kernel(float* __restrict__ out) {
    out[LOSS_OFF] = 0.25f * g_loss * (1.f / (float)(NVEC * DIM));
}

extern "C" void kernel_launch(void* const* d_in, const int* in_sizes, int n_in,
                              void* d_out, int out_size) {
    const float* in  = (const float*)d_in[0];  // [16,64,64,64]
    const float* W   = (const float*)d_in[1];  // [1024,64]
    const float* ecs = (const float*)d_in[2];  // [1024]
    const float* emw = (const float*)d_in[3];  // [1024,64]
    float* out = (float*)d_out;

    cudaFuncSetAttribute(argmin_kernel,
                         cudaFuncAttributeMaxDynamicSharedMemorySize, SMEM_ARG);

    prep_kernel<<<256, 256>>>(W);
    argmin_kernel<<<GRID_ARG, 128, SMEM_ARG>>>(in);
    update_kernel<<<1, 1024>>>(ecs, emw, out);
    quant_kernel<<<1024, 256>>>(in, out);
    loss_kernel<<<1, 1>>>(out);
}

// round 9
// speedup vs baseline: 1.0383x; 1.0383x over previous
#include <cuda_runtime.h>
#include <cuda_bf16.h>
#include <cstdint>

// Problem constants
#define NVEC   65536      // N = B*H*W = 16*64*64
#define KCODE  1024
#define DIM    64
#define HW     4096       // H*W
#define CHW    262144     // C*H*W

// Output layout (concatenated in reference return order, all fp32)
#define QUANT_OFF 0
#define LOSS_OFF  4194304
#define PERP_OFF  4194305
#define NCS_OFF   4194306
#define EMAW_OFF  4195330
#define EMBW_OFF  4260866

#define NTILES   1024     // 64-row work tiles
#define GRID_ARG 296      // 148 SMs * 2 blocks (80KB smem each)
#define SMEM_ARG 81920    // 20480 floats: xs 4096 + ws0 8192 + ws1 8192

// Scratch (device globals — no allocation allowed)
__device__ int   g_idx[NVEC];
__device__ __align__(16) float g_Wt[DIM * KCODE];     // Wt[d][k]
__device__ float g_w2[KCODE];
__device__ int   g_counts[KCODE];
__device__ __align__(16) float g_dw[KCODE * DIM];
__device__ __align__(16) float g_embed[KCODE * DIM];  // aligned copy of new codebook
__device__ float g_loss;
__device__ int   g_tile;

// ---------------------------------------------------------------------------
// Kernel A: prep — transpose W, ||w||^2, zero accumulators, reset tile counter
// ---------------------------------------------------------------------------
__global__ void prep_kernel(const float* __restrict__ W) {
    int i = blockIdx.x * 256 + threadIdx.x;   // 0..65535
    g_dw[i] = 0.f;
    int d = i >> 10;
    int k = i & 1023;
    g_Wt[i] = W[k * DIM + d];
    if (i < KCODE) {
        g_counts[i] = 0;
        const float* row = W + i * DIM;
        float s = 0.f;
        #pragma unroll
        for (int dd = 0; dd < DIM; ++dd) {
            float v = row[dd];
            s = fmaf(v, v, s);
        }
        g_w2[i] = s;
    }
    if (i == 0) { g_loss = 0.f; g_tile = 0; }
}

// cp.async a full 64x128 W tile (32KB) into a ws buffer, 16 x 16B per thread
__device__ __forceinline__ void cp_ws_tile(float* ws, int t8, int tid) {
    const float* base = g_Wt + t8 * 128;
    #pragma unroll
    for (int i = 0; i < 16; ++i) {
        int fidx = i * 128 + tid;          // float4 index over 64x32
        int d  = fidx >> 5;
        int c4 = fidx & 31;
        unsigned dst = (unsigned)__cvta_generic_to_shared(ws + d * 128 + c4 * 4);
        const float* sp = base + d * KCODE + c4 * 4;
        asm volatile("cp.async.cg.shared.global [%0], [%1], 16;\n"
                     :: "r"(dst), "l"(sp));
    }
    asm volatile("cp.async.commit_group;\n" ::: "memory");
}

// ---------------------------------------------------------------------------
// Kernel B: persistent fused distance-GEMM + argmin + counts + dw scatter.
// R5 geometry (128 threads; 64 rows x 128-code tiles; 8x8 thread tile;
// 1 B/MAC smem traffic) + double-buffered cp.async W prefetch so no LDG
// latency is ever exposed. Dynamic smem 80KB -> 2 blocks/SM.
// Per-thread dot = same sequential fp32 chain as R5 -> identical argmins.
// ---------------------------------------------------------------------------
__global__ void __launch_bounds__(128) argmin_kernel(const float* __restrict__ in) {
    extern __shared__ float sm[];
    float* xs  = sm;                       // xs[d*64 + c], 16KB
    float* ws0 = sm + 4096;                // ws[d*128 + k], 32KB
    float* ws1 = sm + 12288;               // second buffer, 32KB
    float* rv  = ws0;                      // overlay: rv[row*16+tx]
    int*   ri  = (int*)(ws0 + 1024);       // overlay: ri[row*16+tx]

    const int tid = threadIdx.x;     // 0..127
    const int tx  = tid & 15;        // code group (16 x 8 codes)
    const int ty  = tid >> 4;        // row group  (8 x 8 rows)

    for (;;) {
        if (tid == 0)
            *reinterpret_cast<volatile int*>(&xs[0]) = atomicAdd(&g_tile, 1);
        __syncthreads();
        const int tile = *reinterpret_cast<volatile int*>(&xs[0]);
        __syncthreads();              // all threads read tile before xs overwrite
        if (tile >= NTILES) return;

        const int n0  = tile * 64;
        const int b   = n0 >> 12;        // 4096 rows per image
        const int hw0 = n0 & 4095;

        // prefetch code tile 0 into ws0 (overlaps the x-tile LDGs below)
        cp_ws_tile(ws0, 0, tid);

        // --- load x tile: xs[d*64+c] = in[b*CHW + d*HW + hw0 + c], coalesced
        const float* src = in + (size_t)b * CHW + hw0;
        #pragma unroll
        for (int i = 0; i < 8; ++i) {
            int fidx = i * 128 + tid;          // float4 index over 64x16
            int d  = fidx >> 4;
            int c4 = fidx & 15;
            float4 v = __ldg(reinterpret_cast<const float4*>(src + d * HW + c4 * 4));
            *reinterpret_cast<float4*>(&xs[d * 64 + c4 * 4]) = v;
        }

        float minv[8];
        int   mink[8];
        #pragma unroll
        for (int r = 0; r < 8; ++r) { minv[r] = 3.4e38f; mink[r] = 0; }

        for (int t8 = 0; t8 < 8; ++t8) {
            float* cur = (t8 & 1) ? ws1 : ws0;
            float* nxt = (t8 & 1) ? ws0 : ws1;

            asm volatile("cp.async.wait_group 0;\n" ::: "memory");
            __syncthreads();   // cur buffer ready; all warps done with nxt (tile t8-1)

            if (t8 < 7) cp_ws_tile(nxt, t8 + 1, tid);   // in flight during compute

            float acc[8][8];
            #pragma unroll
            for (int r = 0; r < 8; ++r)
                #pragma unroll
                for (int j = 0; j < 8; ++j) acc[r][j] = 0.f;

            #pragma unroll 2
            for (int d = 0; d < DIM; ++d) {
                float4 a0 = *reinterpret_cast<const float4*>(&xs[d * 64 + ty * 8]);
                float4 a1 = *reinterpret_cast<const float4*>(&xs[d * 64 + ty * 8 + 4]);
                float4 b0 = *reinterpret_cast<const float4*>(&cur[d * 128 + tx * 8]);
                float4 b1 = *reinterpret_cast<const float4*>(&cur[d * 128 + tx * 8 + 4]);
                float ar[8] = {a0.x, a0.y, a0.z, a0.w, a1.x, a1.y, a1.z, a1.w};
                float br[8] = {b0.x, b0.y, b0.z, b0.w, b1.x, b1.y, b1.z, b1.w};
                #pragma unroll
                for (int r = 0; r < 8; ++r)
                    #pragma unroll
                    for (int j = 0; j < 8; ++j)
                        acc[r][j] = fmaf(ar[r], br[j], acc[r][j]);
            }

            // epilogue: dist = w2 - 2*dot (x^2 per-row constant, argmin-invariant)
            #pragma unroll
            for (int j = 0; j < 8; ++j) {
                int kg = t8 * 128 + tx * 8 + j;
                float w2v = __ldg(&g_w2[kg]);
                #pragma unroll
                for (int r = 0; r < 8; ++r) {
                    float v = fmaf(-2.f, acc[r][j], w2v);
                    if (v < minv[r]) { minv[r] = v; mink[r] = kg; }
                }
            }
        }

        __syncthreads();   // all compute done (ws0 free for red overlay)

        // --- cross-thread reduction (16 candidates per row)
        #pragma unroll
        for (int r = 0; r < 8; ++r) {
            int row = ty * 8 + r;
            rv[row * 16 + tx] = minv[r];
            ri[row * 16 + tx] = mink[r];
        }
        __syncthreads();

        if (tid < 64) {
            float bv = rv[tid * 16];
            int   bi = ri[tid * 16];
            #pragma unroll
            for (int t = 1; t < 16; ++t) {
                float v  = rv[tid * 16 + t];
                int   ii = ri[tid * 16 + t];
                if (v < bv || (v == bv && ii < bi)) { bv = v; bi = ii; }
            }
            g_idx[n0 + tid] = bi;
            atomicAdd(&g_counts[bi], 1);
            ri[tid * 16] = bi;     // publish for dw scatter
        }
        __syncthreads();

        // --- dw scatter: dw[k][d] += x[n][d] (conflict-free smem reads)
        {
            int row   = tid & 63;
            int dbase = (tid >> 6) * 32;
            int kk = ri[row * 16];
            float* dst = &g_dw[kk * DIM + dbase];
            #pragma unroll
            for (int i = 0; i < 32; ++i)
                atomicAdd(&dst[i], xs[(dbase + i) * 64 + row]);
        }
        __syncthreads();   // protect xs / red before next tile
    }
}

// ---------------------------------------------------------------------------
// Kernel C: codebook EMA update + perplexity (single block, 1024 threads)
// ---------------------------------------------------------------------------
__global__ void update_kernel(const float* __restrict__ ecs,
                              const float* __restrict__ emw,
                              float* __restrict__ out) {
    int k = threadIdx.x;
    __shared__ float smr[KCODE];

    float c   = (float)g_counts[k];
    float ncs = ecs[k] * 0.99f + 0.01f * c;
    out[NCS_OFF + k] = ncs;

    smr[k] = ncs; __syncthreads();
    for (int s = 512; s > 0; s >>= 1) {
        if (k < s) smr[k] += smr[k + s];
        __syncthreads();
    }
    float nsum = smr[0];
    __syncthreads();

    float p = c * (1.f / (float)NVEC);
    smr[k] = p * logf(p + 1e-10f);
    __syncthreads();
    for (int s = 512; s > 0; s >>= 1) {
        if (k < s) smr[k] += smr[k + s];
        __syncthreads();
    }
    if (k == 0) out[PERP_OFF] = expf(-smr[0]);

    float normalized = (ncs + 1e-5f) / (nsum + 1024.f * 1e-5f) * nsum;
    float inv = 1.f / normalized;
    #pragma unroll
    for (int d = 0; d < DIM; ++d) {
        int i = k * DIM + d;
        float nw = emw[i] * 0.99f + 0.01f * g_dw[i];
        float e  = nw * inv;
        out[EMAW_OFF + i] = nw;
        out[EMBW_OFF + i] = e;
        g_embed[i] = e;            // aligned copy for float4 gathers in quant
    }
}

// ---------------------------------------------------------------------------
// Kernel D: quantize + loss (float4 codebook gathers from aligned g_embed)
// ---------------------------------------------------------------------------
__global__ void quant_kernel(const float* __restrict__ in,
                             float* __restrict__ out) {
    int blk = blockIdx.x;
    int b  = blk >> 6;
    int d0 = ((blk >> 2) & 15) * 4;
    int hc = blk & 3;
    int t  = threadIdx.x;

    const size_t pbase = (size_t)b * CHW + (size_t)d0 * HW;
    const int nbase = b * HW;

    float local = 0.f;
    #pragma unroll
    for (int it = 0; it < 4; ++it) {
        int hw = hc * 1024 + it * 256 + t;
        int kk = g_idx[nbase + hw];
        float4 q = *reinterpret_cast<const float4*>(&g_embed[kk * DIM + d0]);
        float qa[4] = {q.x, q.y, q.z, q.w};
        #pragma unroll
        for (int j = 0; j < 4; ++j) {
            size_t off = pbase + (size_t)j * HW + hw;
            float x = in[off];
            out[QUANT_OFF + off] = qa[j];   // x + (q - x) == q
            float diff = x - qa[j];
            local = fmaf(diff, diff, local);
        }
    }

    #pragma unroll
    for (int o = 16; o > 0; o >>= 1)
        local += __shfl_down_sync(0xffffffff, local, o);
    __shared__ float wsum[8];
    if ((t & 31) == 0) wsum[t >> 5] = local;
    __syncthreads();
    if (t == 0) {
        float s = 0.f;
        #pragma unroll
        for (int i = 0; i < 8; ++i) s += wsum[i];
        atomicAdd(&g_loss, s);
    }
}

__global__ void loss_kernel(float* __restrict__ out) {
    out[LOSS_OFF] = 0.25f * g_loss * (1.f / (float)(NVEC * DIM));
}

extern "C" void kernel_launch(void* const* d_in, const int* in_sizes, int n_in,
                              void* d_out, int out_size) {
    const float* in  = (const float*)d_in[0];  // [16,64,64,64]
    const float* W   = (const float*)d_in[1];  // [1024,64]
    const float* ecs = (const float*)d_in[2];  // [1024]
    const float* emw = (const float*)d_in[3];  // [1024,64]
    float* out = (float*)d_out;

    cudaFuncSetAttribute(argmin_kernel,
                         cudaFuncAttributeMaxDynamicSharedMemorySize, SMEM_ARG);

    prep_kernel<<<256, 256>>>(W);
    argmin_kernel<<<GRID_ARG, 128, SMEM_ARG>>>(in);
    update_kernel<<<1, 1024>>>(ecs, emw, out);
    quant_kernel<<<1024, 256>>>(in, out);
    loss_kernel<<<1, 1>>>(out);
}

// round 10
// speedup vs baseline: 1.1141x; 1.0731x over previous
#include <cuda_runtime.h>
#include <cuda_bf16.h>
#include <cstdint>

// Problem constants
#define NVEC   65536      // N = B*H*W = 16*64*64
#define KCODE  1024
#define DIM    64
#define HW     4096       // H*W
#define CHW    262144     // C*H*W

// Output layout (concatenated in reference return order, all fp32)
#define QUANT_OFF 0
#define LOSS_OFF  4194304
#define PERP_OFF  4194305
#define NCS_OFF   4194306
#define EMAW_OFF  4195330
#define EMBW_OFF  4260866

#define NRT      1024     // 64-row tiles
#define GRID_ARG 296      // 2 halves x 148 slots; 1 block/SM -> 2 waves

// dynamic smem float map: ws[64][512] | w2s[512] | xs0[64][64] | xs1[64][64]
#define WS_F   0
#define W2_F   32768
#define XS0_F  33280
#define XS1_F  37376
#define SMEM_ARG 165888   // bytes (41472 floats)

// Scratch (device globals — no allocation allowed)
__device__ int   g_idx[NVEC];
__device__ __align__(16) float g_Wt[DIM * KCODE];     // Wt[d][k]
__device__ float g_w2[KCODE];
__device__ int   g_counts[KCODE];
__device__ __align__(16) float g_dw[KCODE * DIM];
__device__ __align__(16) float g_embed[KCODE * DIM];
__device__ unsigned long long g_part[2][NVEC];        // packed (odist<<32)|code
__device__ float g_loss;

// ---------------------------------------------------------------------------
// Kernel A: prep — transpose W, ||w||^2, zero accumulators
// ---------------------------------------------------------------------------
__global__ void prep_kernel(const float* __restrict__ W) {
    int i = blockIdx.x * 256 + threadIdx.x;   // 0..65535
    g_dw[i] = 0.f;
    int d = i >> 10;
    int k = i & 1023;
    g_Wt[i] = W[k * DIM + d];
    if (i < KCODE) {
        g_counts[i] = 0;
        const float* row = W + i * DIM;
        float s = 0.f;
        #pragma unroll
        for (int dd = 0; dd < DIM; ++dd) {
            float v = row[dd];
            s = fmaf(v, v, s);
        }
        g_w2[i] = s;
    }
    if (i == 0) g_loss = 0.f;
}

// cp.async one 64-row x tile (16KB) into a xs buffer (4 x 16B per thread)
__device__ __forceinline__ void cp_x_tile(float* buf, const float* __restrict__ in,
                                          int rt, int tid) {
    const int n0  = rt * 64;
    const int b   = n0 >> 12;
    const int hw0 = n0 & 4095;
    const float* src = in + (size_t)b * CHW + hw0;
    #pragma unroll
    for (int it = 0; it < 4; ++it) {
        int fidx = it * 256 + tid;         // float4 index over 64x16
        int d  = fidx >> 4;
        int c4 = fidx & 15;
        unsigned dst = (unsigned)__cvta_generic_to_shared(buf + d * 64 + c4 * 4);
        asm volatile("cp.async.cg.shared.global [%0], [%1], 16;\n"
                     :: "r"(dst), "l"(src + d * HW + c4 * 4));
    }
    asm volatile("cp.async.commit_group;\n" ::: "memory");
}

// ---------------------------------------------------------------------------
// Kernel B: resident-codebook distance + per-half argmin.
// Block owns codes [half*512, half*512+512) in smem for its whole life.
// 256 threads; x tiles of 64 rows, statically strided, cp.async double-buffered.
// Thread tile: 8 rows x 8 codes per 256-code chunk (2 chunks); b-operand LDS
// contiguous per quarter-warp -> conflict-free; a-operands broadcast.
// Row argmin: warp shuffle only. Partials packed to g_part[half][n].
// ---------------------------------------------------------------------------
__global__ void __launch_bounds__(256, 1) argmin_kernel(const float* __restrict__ in) {
    extern __shared__ float sm[];
    float* ws  = sm + WS_F;                 // ws[d*512 + k]
    float* w2s = sm + W2_F;
    float* xs0 = sm + XS0_F;                // xs[d*64 + c]
    float* xs1 = sm + XS1_F;

    const int tid  = threadIdx.x;
    const int tx   = tid & 31;              // lane = code group
    const int ty   = tid >> 5;              // warp = row group (8 rows each)
    const int half = blockIdx.x & 1;
    const int slot = blockIdx.x >> 1;       // 0..147
    const int kbase = half * 512;

    // --- load resident codebook half + w2 (once)
    for (int i = tid; i < 64 * 128; i += 256) {       // 8192 float4
        int d  = i >> 7;
        int c4 = i & 127;
        *reinterpret_cast<float4*>(&ws[d * 512 + c4 * 4]) =
            *reinterpret_cast<const float4*>(&g_Wt[d * 1024 + kbase + c4 * 4]);
    }
    for (int i = tid; i < 512; i += 256) w2s[i] = g_w2[kbase + i];

    const int ntiles = (NRT - 1 - slot) / 148 + 1;    // 6 or 7

    cp_x_tile(xs0, in, slot, tid);                    // prefetch tile 0

    for (int k = 0; k < ntiles; ++k) {
        float* cur = (k & 1) ? xs1 : xs0;
        float* nxt = (k & 1) ? xs0 : xs1;
        const int rt = slot + 148 * k;
        const int n0 = rt * 64;

        __syncthreads();     // everyone done reading 'nxt' (iter k-1); W ready at k=0
        if (k + 1 < ntiles) {
            cp_x_tile(nxt, in, rt + 148, tid);
            asm volatile("cp.async.wait_group 1;\n" ::: "memory");
        } else {
            asm volatile("cp.async.wait_group 0;\n" ::: "memory");
        }
        __syncthreads();     // 'cur' fully populated for all threads

        float minv[8];
        int   mink[8];
        #pragma unroll
        for (int r = 0; r < 8; ++r) { minv[r] = 3.4e38f; mink[r] = 0; }

        #pragma unroll
        for (int ch = 0; ch < 2; ++ch) {
            float acc[8][8];
            #pragma unroll
            for (int r = 0; r < 8; ++r)
                #pragma unroll
                for (int j = 0; j < 8; ++j) acc[r][j] = 0.f;

            const float* wsc = ws + ch * 256;
            #pragma unroll 2
            for (int d = 0; d < DIM; ++d) {
                float4 a0 = *reinterpret_cast<const float4*>(&cur[d * 64 + ty * 8]);
                float4 a1 = *reinterpret_cast<const float4*>(&cur[d * 64 + ty * 8 + 4]);
                float4 b0 = *reinterpret_cast<const float4*>(&wsc[d * 512 + tx * 4]);
                float4 b1 = *reinterpret_cast<const float4*>(&wsc[d * 512 + 128 + tx * 4]);
                float ar[8] = {a0.x, a0.y, a0.z, a0.w, a1.x, a1.y, a1.z, a1.w};
                float br[8] = {b0.x, b0.y, b0.z, b0.w, b1.x, b1.y, b1.z, b1.w};
                #pragma unroll
                for (int r = 0; r < 8; ++r)
                    #pragma unroll
                    for (int j = 0; j < 8; ++j)
                        acc[r][j] = fmaf(ar[r], br[j], acc[r][j]);
            }

            // epilogue: dist = w2 - 2*dot (x^2 per-row constant, argmin-invariant)
            #pragma unroll
            for (int j = 0; j < 8; ++j) {
                int kl = ch * 256 + ((j < 4) ? (tx * 4 + j) : (128 + tx * 4 + j - 4));
                float w2v = w2s[kl];
                #pragma unroll
                for (int r = 0; r < 8; ++r) {
                    float v = fmaf(-2.f, acc[r][j], w2v);
                    if (v < minv[r]) { minv[r] = v; mink[r] = kl; }
                }
            }
        }

        // --- per-row argmin across the 32 lanes (warp-local, no smem)
        #pragma unroll
        for (int r = 0; r < 8; ++r) {
            float bv = minv[r];
            int   bi = mink[r];
            #pragma unroll
            for (int off = 16; off > 0; off >>= 1) {
                float v  = __shfl_down_sync(0xffffffffu, bv, off);
                int   ii = __shfl_down_sync(0xffffffffu, bi, off);
                if (v < bv || (v == bv && ii < bi)) { bv = v; bi = ii; }
            }
            if (tx == 0) {
                uint32_t u = __float_as_uint(bv);
                u = (bv < 0.f) ? ~u : (u | 0x80000000u);   // order-preserving
                g_part[half][n0 + ty * 8 + r] =
                    ((unsigned long long)u << 32) | (uint32_t)(kbase + bi);
            }
        }
    }
}

// ---------------------------------------------------------------------------
// Kernel B2: combine halves -> g_idx, counts, dw scatter (x re-read, coalesced)
// ---------------------------------------------------------------------------
__global__ void combine_kernel(const float* __restrict__ in) {
    int n = blockIdx.x * 256 + threadIdx.x;   // grid 256 -> 65536
    unsigned long long p0 = g_part[0][n];
    unsigned long long p1 = g_part[1][n];
    unsigned long long p  = (p1 < p0) ? p1 : p0;
    int code = (int)(uint32_t)p;
    g_idx[n] = code;
    atomicAdd(&g_counts[code], 1);

    int b  = n >> 12;
    int hw = n & 4095;
    const float* src = in + (size_t)b * CHW + hw;
    float* dst = g_dw + code * DIM;
    #pragma unroll
    for (int d = 0; d < DIM; ++d)
        atomicAdd(&dst[d], src[(size_t)d * HW]);
}

// ---------------------------------------------------------------------------
// Kernel C: codebook EMA update + perplexity (single block, 1024 threads)
// ---------------------------------------------------------------------------
__global__ void update_kernel(const float* __restrict__ ecs,
                              const float* __restrict__ emw,
                              float* __restrict__ out) {
    int k = threadIdx.x;
    __shared__ float smr[KCODE];

    float c   = (float)g_counts[k];
    float ncs = ecs[k] * 0.99f + 0.01f * c;
    out[NCS_OFF + k] = ncs;

    smr[k] = ncs; __syncthreads();
    for (int s = 512; s > 0; s >>= 1) {
        if (k < s) smr[k] += smr[k + s];
        __syncthreads();
    }
    float nsum = smr[0];
    __syncthreads();

    float p = c * (1.f / (float)NVEC);
    smr[k] = p * logf(p + 1e-10f);
    __syncthreads();
    for (int s = 512; s > 0; s >>= 1) {
        if (k < s) smr[k] += smr[k + s];
        __syncthreads();
    }
    if (k == 0) out[PERP_OFF] = expf(-smr[0]);

    float normalized = (ncs + 1e-5f) / (nsum + 1024.f * 1e-5f) * nsum;
    float inv = 1.f / normalized;
    #pragma unroll
    for (int d = 0; d < DIM; ++d) {
        int i = k * DIM + d;
        float nw = emw[i] * 0.99f + 0.01f * g_dw[i];
        float e  = nw * inv;
        out[EMAW_OFF + i] = nw;
        out[EMBW_OFF + i] = e;
        g_embed[i] = e;            // aligned copy for float4 gathers in quant
    }
}

// ---------------------------------------------------------------------------
// Kernel D: quantize + loss (float4 codebook gathers from aligned g_embed)
// ---------------------------------------------------------------------------
__global__ void quant_kernel(const float* __restrict__ in,
                             float* __restrict__ out) {
    int blk = blockIdx.x;
    int b  = blk >> 6;
    int d0 = ((blk >> 2) & 15) * 4;
    int hc = blk & 3;
    int t  = threadIdx.x;

    const size_t pbase = (size_t)b * CHW + (size_t)d0 * HW;
    const int nbase = b * HW;

    float local = 0.f;
    #pragma unroll
    for (int it = 0; it < 4; ++it) {
        int hw = hc * 1024 + it * 256 + t;
        int kk = g_idx[nbase + hw];
        float4 q = *reinterpret_cast<const float4*>(&g_embed[kk * DIM + d0]);
        float qa[4] = {q.x, q.y, q.z, q.w};
        #pragma unroll
        for (int j = 0; j < 4; ++j) {
            size_t off = pbase + (size_t)j * HW + hw;
            float x = in[off];
            out[QUANT_OFF + off] = qa[j];   // x + (q - x) == q
            float diff = x - qa[j];
            local = fmaf(diff, diff, local);
        }
    }

    #pragma unroll
    for (int o = 16; o > 0; o >>= 1)
        local += __shfl_down_sync(0xffffffff, local, o);
    __shared__ float wsum[8];
    if ((t & 31) == 0) wsum[t >> 5] = local;
    __syncthreads();
    if (t == 0) {
        float s = 0.f;
        #pragma unroll
        for (int i = 0; i < 8; ++i) s += wsum[i];
        atomicAdd(&g_loss, s);
    }
}

__global__ void loss_kernel(float* __restrict__ out) {
    out[LOSS_OFF] = 0.25f * g_loss * (1.f / (float)(NVEC * DIM));
}

extern "C" void kernel_launch(void* const* d_in, const int* in_sizes, int n_in,
                              void* d_out, int out_size) {
    const float* in  = (const float*)d_in[0];  // [16,64,64,64]
    const float* W   = (const float*)d_in[1];  // [1024,64]
    const float* ecs = (const float*)d_in[2];  // [1024]
    const float* emw = (const float*)d_in[3];  // [1024,64]
    float* out = (float*)d_out;

    cudaFuncSetAttribute(argmin_kernel,
                         cudaFuncAttributeMaxDynamicSharedMemorySize, SMEM_ARG);

    prep_kernel<<<256, 256>>>(W);
    argmin_kernel<<<GRID_ARG, 256, SMEM_ARG>>>(in);
    combine_kernel<<<256, 256>>>(in);
    update_kernel<<<1, 1024>>>(ecs, emw, out);
    quant_kernel<<<1024, 256>>>(in, out);
    loss_kernel<<<1, 1>>>(out);
}

// round 11
// speedup vs baseline: 1.9526x; 1.7526x over previous
#include <cuda_runtime.h>
#include <cuda_bf16.h>
#include <cstdint>

// Problem constants
#define NVEC   65536      // N = B*H*W = 16*64*64
#define KCODE  1024
#define DIM    64
#define HW     4096       // H*W
#define CHW    262144     // C*H*W

// Output layout (concatenated in reference return order, all fp32)
#define QUANT_OFF 0
#define LOSS_OFF  4194304
#define PERP_OFF  4194305
#define NCS_OFF   4194306
#define EMAW_OFF  4195330
#define EMBW_OFF  4260866

#define NTILES   1024     // 64-row work tiles
#define GRID_ARG 592      // 148 SMs * 4 blocks

// Scratch (device globals — no allocation allowed)
__device__ int   g_idx[NVEC];
__device__ __align__(16) float g_Wt[DIM * KCODE];     // Wt[d][k]
__device__ float g_w2[KCODE];
__device__ int   g_counts[KCODE];
__device__ __align__(16) float g_dw[KCODE * DIM];
__device__ __align__(16) float g_embed[KCODE * DIM];  // aligned copy of new codebook
__device__ float g_inv[KCODE];                        // 1/normalized[k]
__device__ float g_loss;
__device__ int   g_tile;

// ---------------------------------------------------------------------------
// Kernel A: prep — transpose W, ||w||^2, zero accumulators, reset tile counter
// ---------------------------------------------------------------------------
__global__ void prep_kernel(const float* __restrict__ W) {
    int i = blockIdx.x * 256 + threadIdx.x;   // 0..65535
    g_dw[i] = 0.f;
    int d = i >> 10;
    int k = i & 1023;
    g_Wt[i] = W[k * DIM + d];
    if (i < KCODE) {
        g_counts[i] = 0;
        const float* row = W + i * DIM;
        float s = 0.f;
        #pragma unroll
        for (int dd = 0; dd < DIM; ++dd) {
            float v = row[dd];
            s = fmaf(v, v, s);
        }
        g_w2[i] = s;
    }
    if (i == 0) { g_loss = 0.f; g_tile = 0; }
}

// ---------------------------------------------------------------------------
// Kernel B (R5-proven): persistent fused distance-GEMM + argmin + counts + dw.
// 128 threads. Block tile: 64 rows x 128 codes (8 code-tiles). Thread tile:
// 8 rows x 8 codes (1 B/MAC smem traffic, FMA-bound). Smem exactly 48 KB;
// tile index bounced through xs[0][0].
// ---------------------------------------------------------------------------
__global__ void __launch_bounds__(128) argmin_kernel(const float* __restrict__ in) {
    __shared__ __align__(16) float xs[DIM][64];      // 16 KB, xs[d][row]
    __shared__ union USm {
        float ws[DIM][128];                          // 32 KB, ws[d][k]
        struct { float rv[64][16]; int ri[64][16]; } red;   // 8 KB overlay
    } u;

    const int tid = threadIdx.x;     // 0..127
    const int tx  = tid & 15;        // code group (16 x 8 codes)
    const int ty  = tid >> 4;        // row group  (8 x 8 rows)

    for (;;) {
        if (tid == 0)
            *reinterpret_cast<volatile int*>(&xs[0][0]) = atomicAdd(&g_tile, 1);
        __syncthreads();
        const int tile = *reinterpret_cast<volatile int*>(&xs[0][0]);
        __syncthreads();              // all threads read tile before xs overwrite
        if (tile >= NTILES) return;

        const int n0  = tile * 64;
        const int b   = n0 >> 12;        // 4096 rows per image
        const int hw0 = n0 & 4095;

        // --- load x tile: xs[d][c] = in[b*CHW + d*HW + hw0 + c], coalesced
        const float* src = in + (size_t)b * CHW + hw0;
        #pragma unroll
        for (int i = 0; i < 8; ++i) {
            int fidx = i * 128 + tid;          // float4 index over 64x16
            int d  = fidx >> 4;
            int c4 = fidx & 15;
            float4 v = __ldg(reinterpret_cast<const float4*>(src + d * HW + c4 * 4));
            *reinterpret_cast<float4*>(&xs[d][c4 * 4]) = v;
        }

        float minv[8];
        int   mink[8];
        #pragma unroll
        for (int r = 0; r < 8; ++r) { minv[r] = 3.4e38f; mink[r] = 0; }

        __syncthreads();

        for (int t8 = 0; t8 < 8; ++t8) {
            // load 64x128 code tile (g_Wt is [d][k] -> coalesced)
            #pragma unroll
            for (int i = 0; i < 16; ++i) {
                int fidx = i * 128 + tid;      // float4 index over 64x32
                int d  = fidx >> 5;
                int c4 = fidx & 31;
                float4 v = __ldg(reinterpret_cast<const float4*>(
                                 &g_Wt[d * KCODE + t8 * 128 + c4 * 4]));
                *reinterpret_cast<float4*>(&u.ws[d][c4 * 4]) = v;
            }
            __syncthreads();

            float acc[8][8];
            #pragma unroll
            for (int r = 0; r < 8; ++r)
                #pragma unroll
                for (int j = 0; j < 8; ++j) acc[r][j] = 0.f;

            #pragma unroll 2
            for (int d = 0; d < DIM; ++d) {
                float4 a0 = *reinterpret_cast<const float4*>(&xs[d][ty * 8]);
                float4 a1 = *reinterpret_cast<const float4*>(&xs[d][ty * 8 + 4]);
                float4 b0 = *reinterpret_cast<const float4*>(&u.ws[d][tx * 8]);
                float4 b1 = *reinterpret_cast<const float4*>(&u.ws[d][tx * 8 + 4]);
                float ar[8] = {a0.x, a0.y, a0.z, a0.w, a1.x, a1.y, a1.z, a1.w};
                float br[8] = {b0.x, b0.y, b0.z, b0.w, b1.x, b1.y, b1.z, b1.w};
                #pragma unroll
                for (int r = 0; r < 8; ++r)
                    #pragma unroll
                    for (int j = 0; j < 8; ++j)
                        acc[r][j] = fmaf(ar[r], br[j], acc[r][j]);
            }

            // epilogue: dist = w2 - 2*dot (x^2 per-row constant, argmin-invariant)
            #pragma unroll
            for (int j = 0; j < 8; ++j) {
                int kg = t8 * 128 + tx * 8 + j;
                float w2v = __ldg(&g_w2[kg]);
                #pragma unroll
                for (int r = 0; r < 8; ++r) {
                    float v = fmaf(-2.f, acc[r][j], w2v);
                    if (v < minv[r]) { minv[r] = v; mink[r] = kg; }
                }
            }
            __syncthreads();   // before overwriting ws / red
        }

        // --- cross-thread reduction (16 candidates per row)
        #pragma unroll
        for (int r = 0; r < 8; ++r) {
            int row = ty * 8 + r;
            u.red.rv[row][tx] = minv[r];
            u.red.ri[row][tx] = mink[r];
        }
        __syncthreads();

        if (tid < 64) {
            float bv = u.red.rv[tid][0];
            int   bi = u.red.ri[tid][0];
            #pragma unroll
            for (int t = 1; t < 16; ++t) {
                float v  = u.red.rv[tid][t];
                int   ii = u.red.ri[tid][t];
                if (v < bv || (v == bv && ii < bi)) { bv = v; bi = ii; }
            }
            g_idx[n0 + tid] = bi;
            atomicAdd(&g_counts[bi], 1);
            u.red.ri[tid][0] = bi;     // publish for dw scatter
        }
        __syncthreads();

        // --- dw scatter: dw[k][d] += x[n][d] (conflict-free smem reads)
        {
            int row   = tid & 63;
            int dbase = (tid >> 6) * 32;
            int kk = u.red.ri[row][0];
            float* dst = &g_dw[kk * DIM + dbase];
            #pragma unroll
            for (int i = 0; i < 32; ++i)
                atomicAdd(&dst[i], xs[dbase + i][row]);
        }
        __syncthreads();   // protect xs / red before next tile
    }
}

// ---------------------------------------------------------------------------
// Kernel C1: scalar codebook stats — ncs, nsum, perplexity, 1/normalized.
// Single block, 1024 threads; only 1024-element coalesced traffic.
// ---------------------------------------------------------------------------
__global__ void update1_kernel(const float* __restrict__ ecs,
                               float* __restrict__ out) {
    int k = threadIdx.x;
    __shared__ float smr[KCODE];

    float c   = (float)g_counts[k];
    float ncs = ecs[k] * 0.99f + 0.01f * c;
    out[NCS_OFF + k] = ncs;

    smr[k] = ncs; __syncthreads();
    for (int s = 512; s > 0; s >>= 1) {
        if (k < s) smr[k] += smr[k + s];
        __syncthreads();
    }
    float nsum = smr[0];
    __syncthreads();

    float p = c * (1.f / (float)NVEC);
    smr[k] = p * logf(p + 1e-10f);
    __syncthreads();
    for (int s = 512; s > 0; s >>= 1) {
        if (k < s) smr[k] += smr[k + s];
        __syncthreads();
    }
    if (k == 0) out[PERP_OFF] = expf(-smr[0]);

    float normalized = (ncs + 1e-5f) / (nsum + 1024.f * 1e-5f) * nsum;
    g_inv[k] = 1.f / normalized;
}

// ---------------------------------------------------------------------------
// Kernel C2: grid-wide coalesced EMA-w + embed write (was the hidden 158us).
// i runs over all 65536 (k,d): adjacent threads -> adjacent 4B addresses.
// ---------------------------------------------------------------------------
__global__ void update2_kernel(const float* __restrict__ emw,
                               float* __restrict__ out) {
    int i = blockIdx.x * 256 + threadIdx.x;   // 0..65535
    int k = i >> 6;
    float nw = emw[i] * 0.99f + 0.01f * g_dw[i];
    float e  = nw * g_inv[k];
    out[EMAW_OFF + i] = nw;
    out[EMBW_OFF + i] = e;
    g_embed[i] = e;            // aligned copy for float4 gathers in quant
}

// ---------------------------------------------------------------------------
// Kernel D: quantize + loss (float4 codebook gathers from aligned g_embed)
// ---------------------------------------------------------------------------
__global__ void quant_kernel(const float* __restrict__ in,
                             float* __restrict__ out) {
    int blk = blockIdx.x;
    int b  = blk >> 6;
    int d0 = ((blk >> 2) & 15) * 4;
    int hc = blk & 3;
    int t  = threadIdx.x;

    const size_t pbase = (size_t)b * CHW + (size_t)d0 * HW;
    const int nbase = b * HW;

    float local = 0.f;
    #pragma unroll
    for (int it = 0; it < 4; ++it) {
        int hw = hc * 1024 + it * 256 + t;
        int kk = g_idx[nbase + hw];
        float4 q = *reinterpret_cast<const float4*>(&g_embed[kk * DIM + d0]);
        float qa[4] = {q.x, q.y, q.z, q.w};
        #pragma unroll
        for (int j = 0; j < 4; ++j) {
            size_t off = pbase + (size_t)j * HW + hw;
            float x = in[off];
            out[QUANT_OFF + off] = qa[j];   // x + (q - x) == q
            float diff = x - qa[j];
            local = fmaf(diff, diff, local);
        }
    }

    #pragma unroll
    for (int o = 16; o > 0; o >>= 1)
        local += __shfl_down_sync(0xffffffff, local, o);
    __shared__ float wsum[8];
    if ((t & 31) == 0) wsum[t >> 5] = local;
    __syncthreads();
    if (t == 0) {
        float s = 0.f;
        #pragma unroll
        for (int i = 0; i < 8; ++i) s += wsum[i];
        atomicAdd(&g_loss, s);
    }
}

__global__ void loss_kernel(float* __restrict__ out) {
    out[LOSS_OFF] = 0.25f * g_loss * (1.f / (float)(NVEC * DIM));
}

extern "C" void kernel_launch(void* const* d_in, const int* in_sizes, int n_in,
                              void* d_out, int out_size) {
    const float* in  = (const float*)d_in[0];  // [16,64,64,64]
    const float* W   = (const float*)d_in[1];  // [1024,64]
    const float* ecs = (const float*)d_in[2];  // [1024]
    const float* emw = (const float*)d_in[3];  // [1024,64]
    float* out = (float*)d_out;

    prep_kernel<<<256, 256>>>(W);
    argmin_kernel<<<GRID_ARG, 128>>>(in);
    update1_kernel<<<1, 1024>>>(ecs, out);
    update2_kernel<<<256, 256>>>(emw, out);
    quant_kernel<<<1024, 256>>>(in, out);
    loss_kernel<<<1, 1>>>(out);
}